// round 2
// baseline (speedup 1.0000x reference)
#include <cuda_runtime.h>

// Degree-2 Taylor attention with RPE, fp32, via packed f32x2 FMA (Blackwell FFMA2).
// B*H=16, N=1024, D=64.  z_ij = q_i.k_j + q_i.rpe[i-j+N-1]; s=1+z+z^2/2; o=Sv/sum(s).

using ull = unsigned long long;

constexpr int NSEQ = 1024;
constexpr int DD   = 64;
constexpr int BI   = 128;
constexpr int BJ   = 128;

constexpr int QS_STR = 160;  // Q^T [64 d][128 + rot<=28 + pad]
constexpr int KS_STR = 160;  // K^T [64 d][128 + rot + pad]
constexpr int RS_STR = 288;  // band^T [64 d][255 + rot + pad]
constexpr int VS_STR = 68;   // V [128 j][64 d + pad]
constexpr int SS_STR = 132;  // S^T [128 j][128 i + pad]  (aliases R region)

constexpr int Q_OFF = 0;
constexpr int K_OFF = Q_OFF + 64 * QS_STR;        // 10240
constexpr int R_OFF = K_OFF + 64 * KS_STR;        // 20480
constexpr int S_OFF = R_OFF;                      // alias (16896 <= 18432)
constexpr int V_OFF = R_OFF + 64 * RS_STR;        // 38912
constexpr int D_OFF = V_OFF + 128 * VS_STR;       // 47616
constexpr int SM_FLOATS = D_OFF + 160;            // ~186.6 KB

__forceinline__ __device__ ull pk(float lo, float hi) {
    ull r; asm("mov.b64 %0, {%1,%2};" : "=l"(r) : "f"(lo), "f"(hi)); return r;
}
__forceinline__ __device__ void upk(float& lo, float& hi, ull v) {
    asm("mov.b64 {%0,%1}, %2;" : "=f"(lo), "=f"(hi) : "l"(v));
}
__forceinline__ __device__ void ffma2(ull& d, ull a, ull b) {
    asm("fma.rn.f32x2 %0, %1, %2, %0;" : "+l"(d) : "l"(a), "l"(b));
}
__forceinline__ __device__ ull ffma2v(ull a, ull b, ull c) {
    ull d; asm("fma.rn.f32x2 %0, %1, %2, %3;" : "=l"(d) : "l"(a), "l"(b), "l"(c)); return d;
}
__forceinline__ __device__ ull fadd2(ull a, ull b) {
    ull d; asm("add.rn.f32x2 %0, %1, %2;" : "=l"(d) : "l"(a), "l"(b)); return d;
}

__global__ void __launch_bounds__(256, 1)
fast_attn_kernel(const float* __restrict__ q, const float* __restrict__ k,
                 const float* __restrict__ v, const float* __restrict__ rpe,
                 float* __restrict__ out)
{
    extern __shared__ float sm[];

    const int bh = blockIdx.y;
    const int i0 = blockIdx.x * BI;
    const int t  = threadIdx.x;
    const int ti = t >> 4;                 // 0..15 : owns rows ti*8..ti*8+7
    const int tj = t & 15;                 // 0..15 : GEMM1 cols tj*8.., GEMM2 d-cols tj*4..
    const int cb = ti * 8 - tj * 8 + 120;  // band window base within 255-wide tile window

    const float* qb = q + (size_t)bh * NSEQ * DD;
    const float* kb = k + (size_t)bh * NSEQ * DD;
    const float* vb = v + (size_t)bh * NSEQ * DD;

    // ---- Q tile transposed, rotation swizzle rot = 4*((d>>2)&7) (once) ----
    #pragma unroll
    for (int it = 0; it < 8; ++it) {
        int idx = t + it * 256;
        int c = idx >> 4, c4 = idx & 15;
        float4 val = *(const float4*)(qb + (size_t)(i0 + c) * DD + (c4 << 2));
        float* dst = sm + Q_OFF + (c4 << 2) * QS_STR + c + ((c4 & 7) << 2);
        dst[0*QS_STR] = val.x; dst[1*QS_STR] = val.y;
        dst[2*QS_STR] = val.z; dst[3*QS_STR] = val.w;
    }

    ull oacc[4][4];   // lanes = (row 2*ii2, row 2*ii2+1), col tj*4+dd
    ull dp[4];
    #pragma unroll
    for (int a = 0; a < 4; ++a) {
        dp[a] = 0ull;
        #pragma unroll
        for (int b = 0; b < 4; ++b) oacc[a][b] = 0ull;
    }
    const ull one2  = pk(1.0f, 1.0f);
    const ull half2 = pk(0.5f, 0.5f);

    for (int j0 = 0; j0 < NSEQ; j0 += BJ) {
        __syncthreads();   // prev GEMM2 done with S(=R)/V before reload

        // ---- K tile transposed ----
        #pragma unroll
        for (int it = 0; it < 8; ++it) {
            int idx = t + it * 256;
            int c = idx >> 4, c4 = idx & 15;
            float4 val = *(const float4*)(kb + (size_t)(j0 + c) * DD + (c4 << 2));
            float* dst = sm + K_OFF + (c4 << 2) * KS_STR + c + ((c4 & 7) << 2);
            dst[0*KS_STR] = val.x; dst[1*KS_STR] = val.y;
            dst[2*KS_STR] = val.z; dst[3*KS_STR] = val.w;
        }
        // ---- V tile ----
        #pragma unroll
        for (int it = 0; it < 8; ++it) {
            int idx = t + it * 256;
            int r = idx >> 4, c4 = idx & 15;
            *(float4*)(sm + V_OFF + r * VS_STR + (c4 << 2)) =
                *(const float4*)(vb + (size_t)(j0 + r) * DD + (c4 << 2));
        }
        // ---- rpe band transposed: rows r0..r0+254, r0 = i0-j0+896 in [0,2046-254] ----
        {
            const int r0 = i0 - j0 + (NSEQ - 1) - (BJ - 1);
            #pragma unroll
            for (int it = 0; it < 16; ++it) {
                int idx = t + it * 256;
                int c = idx >> 4, c4 = idx & 15;
                if (c < 255) {
                    float4 val = *(const float4*)(rpe + (size_t)(r0 + c) * DD + (c4 << 2));
                    float* dst = sm + R_OFF + (c4 << 2) * RS_STR + c + ((c4 & 7) << 2);
                    dst[0*RS_STR] = val.x; dst[1*RS_STR] = val.y;
                    dst[2*RS_STR] = val.z; dst[3*RS_STR] = val.w;
                }
            }
        }
        __syncthreads();

        // ---- GEMM1 (packed along ii): z2[ii2][jj], lanes (2ii2, 2ii2+1) ----
        ull z2[4][8];
        #pragma unroll
        for (int a = 0; a < 4; ++a)
            #pragma unroll
            for (int b = 0; b < 8; ++b) z2[a][b] = 0ull;

        #pragma unroll 2
        for (int d = 0; d < DD; ++d) {
            const int rot = ((d >> 2) & 7) << 2;
            const float* qrow = sm + Q_OFF + d * QS_STR + rot + ti * 8;
            ulonglong2 qa = *(const ulonglong2*)(qrow);
            ulonglong2 qc = *(const ulonglong2*)(qrow + 4);
            ull a2[4] = { qa.x, qa.y, qc.x, qc.y };

            const float* krow = sm + K_OFF + d * KS_STR + rot + tj * 8;
            float4 kb0 = *(const float4*)(krow);
            float4 kb1 = *(const float4*)(krow + 4);
            ull b2[8] = { pk(kb0.x,kb0.x), pk(kb0.y,kb0.y), pk(kb0.z,kb0.z), pk(kb0.w,kb0.w),
                          pk(kb1.x,kb1.x), pk(kb1.y,kb1.y), pk(kb1.z,kb1.z), pk(kb1.w,kb1.w) };

            const float* rrow = sm + R_OFF + d * RS_STR + rot + cb;
            float4 rr0 = *(const float4*)(rrow);
            float4 rr1 = *(const float4*)(rrow + 4);
            float4 rr2 = *(const float4*)(rrow + 8);
            float4 rr3 = *(const float4*)(rrow + 12);
            float rf[16] = { rr0.x,rr0.y,rr0.z,rr0.w, rr1.x,rr1.y,rr1.z,rr1.w,
                             rr2.x,rr2.y,rr2.z,rr2.w, rr3.x,rr3.y,rr3.z,rr3.w };
            ull rp[14];
            #pragma unroll
            for (int c = 0; c < 14; ++c) rp[c] = pk(rf[c], rf[c+1]);

            #pragma unroll
            for (int ii2 = 0; ii2 < 4; ++ii2) {
                #pragma unroll
                for (int jj = 0; jj < 8; ++jj) {
                    ffma2(z2[ii2][jj], a2[ii2], b2[jj]);              // q.k
                    ffma2(z2[ii2][jj], a2[ii2], rp[2*ii2 + 7 - jj]);  // band
                }
            }
        }

        // ---- transform in place: s = 1 + z + 0.5 z^2 ; accumulate denominators ----
        #pragma unroll
        for (int ii2 = 0; ii2 < 4; ++ii2) {
            #pragma unroll
            for (int jj = 0; jj < 8; ++jj) {
                ull zz = z2[ii2][jj];
                ull tt = ffma2v(zz, half2, one2);
                ull ss = ffma2v(zz, tt, one2);
                z2[ii2][jj] = ss;
                dp[ii2] = fadd2(dp[ii2], ss);
            }
        }
        __syncthreads();   // all band reads done before S^T overwrites R region

        // ---- store S^T[j][i] as packed 64-bit, jj staggered by tj ----
        #pragma unroll
        for (int ii2 = 0; ii2 < 4; ++ii2) {
            #pragma unroll
            for (int jx = 0; jx < 8; ++jx) {
                int jj = (jx + tj) & 7;
                *(ull*)(sm + S_OFF + (tj*8 + jj) * SS_STR + ti*8 + ii2*2) = z2[ii2][jj];
            }
        }
        __syncthreads();

        // ---- GEMM2: o2[ii2][dd] += s2[ii2] * dup(v[j][dd]) ----
        #pragma unroll 4
        for (int j = 0; j < BJ; ++j) {
            const float* srow = sm + S_OFF + j * SS_STR + ti * 8;
            ulonglong2 sa = *(const ulonglong2*)(srow);
            ulonglong2 sc = *(const ulonglong2*)(srow + 4);
            ull s2[4] = { sa.x, sa.y, sc.x, sc.y };
            float4 vv = *(const float4*)(sm + V_OFF + j * VS_STR + tj * 4);
            ull v2[4] = { pk(vv.x,vv.x), pk(vv.y,vv.y), pk(vv.z,vv.z), pk(vv.w,vv.w) };
            #pragma unroll
            for (int ii2 = 0; ii2 < 4; ++ii2) {
                #pragma unroll
                for (int dd = 0; dd < 4; ++dd)
                    ffma2(oacc[ii2][dd], s2[ii2], v2[dd]);
            }
        }
    }

    // ---- reduce denominators across the 16 tj threads (64-bit shuffles) ----
    #pragma unroll
    for (int ii2 = 0; ii2 < 4; ++ii2) {
        ull dsum = dp[ii2];
        #pragma unroll
        for (int off = 8; off > 0; off >>= 1)
            dsum += 0;  // placeholder to keep unroll structure
        // 64-bit packed shuffle-add
        #pragma unroll
        for (int off = 8; off > 0; off >>= 1) {
            ull other = __shfl_down_sync(0xffffffffu, dsum, off, 16);
            dsum = fadd2(dsum, other);
        }
        if (tj == 0) {
            float lo, hi; upk(lo, hi, dsum);
            sm[D_OFF + ti*8 + ii2*2 + 0] = lo;
            sm[D_OFF + ti*8 + ii2*2 + 1] = hi;
        }
    }
    __syncthreads();

    // ---- epilogue: divide and store ----
    float* ob = out + ((size_t)bh * NSEQ + i0) * DD;
    #pragma unroll
    for (int ii2 = 0; ii2 < 4; ++ii2) {
        const float inv0 = 1.0f / sm[D_OFF + ti*8 + ii2*2 + 0];
        const float inv1 = 1.0f / sm[D_OFF + ti*8 + ii2*2 + 1];
        float o0[4], o1[4];
        #pragma unroll
        for (int dd = 0; dd < 4; ++dd) upk(o0[dd], o1[dd], oacc[ii2][dd]);
        float4 w0 = make_float4(o0[0]*inv0, o0[1]*inv0, o0[2]*inv0, o0[3]*inv0);
        float4 w1 = make_float4(o1[0]*inv1, o1[1]*inv1, o1[2]*inv1, o1[3]*inv1);
        *(float4*)(ob + (size_t)(ti*8 + ii2*2 + 0) * DD + tj*4) = w0;
        *(float4*)(ob + (size_t)(ti*8 + ii2*2 + 1) * DD + tj*4) = w1;
    }
}

extern "C" void kernel_launch(void* const* d_in, const int* in_sizes, int n_in,
                              void* d_out, int out_size)
{
    const float* q   = (const float*)d_in[0];
    const float* k   = (const float*)d_in[1];
    const float* v   = (const float*)d_in[2];
    // d_in[3] = drop_noise (unused)
    const float* rpe = (const float*)d_in[4];
    float* out = (float*)d_out;

    const size_t smem = SM_FLOATS * sizeof(float);
    cudaFuncSetAttribute(fast_attn_kernel,
                         cudaFuncAttributeMaxDynamicSharedMemorySize, (int)smem);
    dim3 grid(NSEQ / BI, 16);   // 8 x 16 = 128 CTAs
    fast_attn_kernel<<<grid, 256, smem>>>(q, k, v, rpe, out);
}

// round 5
// speedup vs baseline: 1.1741x; 1.1741x over previous
#include <cuda_runtime.h>
#include <cuda_bf16.h>
#include <cstdint>

// Degree-2 Taylor attention with RPE via warp-level mma.sync (bf16 x3-split).
// z_ij = q_i.k_j + q_i.rpe[i-j+1023]; s = 1+z+z^2/2; o = (S v)/rowsum(S).
// BI=BJ=64, grid 16 i-tiles x 16 bh, 256 threads (8 warps), 2 CTAs/SM.

constexpr int NSEQ = 1024, BI = 64, BJ = 64, NT = NSEQ / BJ;

// smem byte offsets (all tiles row-major bf16, 128B rows, XOR-16B swizzle)
constexpr int Q_HI = 0,      Q_LO = 8192;
constexpr int K_HI = 16384,  K_LO = 24576;
constexpr int R_HI = 32768,  R_LO = 49152;   // 128 rows x 128B each
constexpr int VT_HI = 65536, VT_LO = 73728;  // V^T 64x64
constexpr int S_HI = 81920,  S_LO = 90112;   // S 64x64 hi/lo
constexpr int STG  = 81920;                  // f32 band stage 64x64 (aliases S)
constexpr int DEN  = 98304;                  // 64 f32
constexpr int SMEM_BYTES = 98560;

#define SWZ(o) ((o) ^ ((((o) >> 7) & 7) << 4))

__device__ __forceinline__ uint32_t smem_u32(const void* p) {
    uint32_t a;
    asm("{ .reg .u64 t; cvta.to.shared.u64 t, %1; cvt.u32.u64 %0, t; }"
        : "=r"(a) : "l"(p));
    return a;
}
__device__ __forceinline__ void ldmA(uint32_t a[4], uint32_t addr) {
    asm volatile("ldmatrix.sync.aligned.m8n8.x4.shared.b16 {%0,%1,%2,%3}, [%4];"
                 : "=r"(a[0]), "=r"(a[1]), "=r"(a[2]), "=r"(a[3]) : "r"(addr));
}
__device__ __forceinline__ void ldmB(uint32_t b[2], uint32_t addr) {
    asm volatile("ldmatrix.sync.aligned.m8n8.x2.shared.b16 {%0,%1}, [%2];"
                 : "=r"(b[0]), "=r"(b[1]) : "r"(addr));
}
__device__ __forceinline__ void mma16816(float d[4], const uint32_t a[4],
                                         const uint32_t b[2]) {
    asm volatile(
        "mma.sync.aligned.m16n8k16.row.col.f32.bf16.bf16.f32 "
        "{%0,%1,%2,%3}, {%4,%5,%6,%7}, {%8,%9}, {%0,%1,%2,%3};"
        : "+f"(d[0]), "+f"(d[1]), "+f"(d[2]), "+f"(d[3])
        : "r"(a[0]), "r"(a[1]), "r"(a[2]), "r"(a[3]), "r"(b[0]), "r"(b[1]));
}
__device__ __forceinline__ void cvt_pair(float a, float b, uint32_t& hi, uint32_t& lo) {
    __nv_bfloat162 h = __floats2bfloat162_rn(a, b);
    float2 hf = __bfloat1622float2(h);
    __nv_bfloat162 l = __floats2bfloat162_rn(a - hf.x, b - hf.y);
    hi = *(uint32_t*)&h;
    lo = *(uint32_t*)&l;
}

__global__ void __launch_bounds__(256, 2)
fast_attn_hmma(const float* __restrict__ q, const float* __restrict__ k,
               const float* __restrict__ v, const float* __restrict__ rpe,
               float* __restrict__ out)
{
    extern __shared__ __align__(1024) char smc[];
    const uint32_t sb = smem_u32(smc);
    float* Pst = (float*)(smc + STG);
    float* Dsm = (float*)(smc + DEN);

    const int bh = blockIdx.y;
    const int i0 = blockIdx.x * BI;
    const int t = threadIdx.x, lane = t & 31, w = t >> 5;
    const int wi = w >> 2, wj = w & 3;          // warp tile: rows wi*32, cols wj*16
    const int qr = lane >> 2, qc = (lane & 3) * 2;

    // ldmatrix per-lane address components (rows are multiples of 8 per frag)
    const uint32_t xl   = (uint32_t)(lane & 7) << 4;   // row-phase XOR for ldmatrix
    const uint32_t xs   = (uint32_t)qr << 4;           // row-phase XOR for S stores
    const uint32_t aoff = ((uint32_t)((lane & 7) + (lane & 8)) << 7) |
                          (((uint32_t)(lane >> 4) & 1) << 4);
    const uint32_t boff = ((uint32_t)(lane & 7) << 7) |
                          (((uint32_t)(lane >> 3) & 1) << 4);

    const float* qb = q + (size_t)bh * NSEQ * 64;
    const float* kb = k + (size_t)bh * NSEQ * 64;
    const float* vb = v + (size_t)bh * NSEQ * 64;

    // ---- convert Q tile once (64x64 -> bf16 hi/lo) ----
    #pragma unroll
    for (int it = 0; it < 4; ++it) {
        int e = t + it * 256;
        int row = e >> 4, c4 = e & 15;
        float4 x = *(const float4*)(qb + (size_t)(i0 + row) * 64 + c4 * 4);
        uint32_t h0, l0, h1, l1;
        cvt_pair(x.x, x.y, h0, l0);
        cvt_pair(x.z, x.w, h1, l1);
        uint32_t sw = SWZ((uint32_t)(row * 128 + c4 * 8));
        *(uint2*)(smc + Q_HI + sw) = make_uint2(h0, h1);
        *(uint2*)(smc + Q_LO + sw) = make_uint2(l0, l1);
    }
    if (t < 64) Dsm[t] = 0.f;

    float oacc[2][2][4];
    float dsum[4];
    #pragma unroll
    for (int a = 0; a < 2; ++a)
        #pragma unroll
        for (int b = 0; b < 2; ++b)
            #pragma unroll
            for (int r = 0; r < 4; ++r) oacc[a][b][r] = 0.f;
    #pragma unroll
    for (int u = 0; u < 4; ++u) dsum[u] = 0.f;

    for (int tile = 0; tile < NT; ++tile) {
        const int j0 = tile * BJ;
        __syncthreads();   // prev SV reads of S/Vt done; smem reuse safe

        // ---- convert K tile ----
        #pragma unroll
        for (int it = 0; it < 4; ++it) {
            int e = t + it * 256;
            int row = e >> 4, c4 = e & 15;
            float4 x = *(const float4*)(kb + (size_t)(j0 + row) * 64 + c4 * 4);
            uint32_t h0, l0, h1, l1;
            cvt_pair(x.x, x.y, h0, l0);
            cvt_pair(x.z, x.w, h1, l1);
            uint32_t sw = SWZ((uint32_t)(row * 128 + c4 * 8));
            *(uint2*)(smc + K_HI + sw) = make_uint2(h0, h1);
            *(uint2*)(smc + K_LO + sw) = make_uint2(l0, l1);
        }
        // ---- convert rpe window rows r0..r0+127 (m = ii-jj+63) ----
        {
            const int r0 = i0 - j0 + 960;
            #pragma unroll
            for (int it = 0; it < 8; ++it) {
                int e = t + it * 256;
                int row = e >> 4, c4 = e & 15;
                int gr = r0 + row; if (gr > 2046) gr = 2046;  // row 127 never gathered
                float4 x = *(const float4*)(rpe + (size_t)gr * 64 + c4 * 4);
                uint32_t h0, l0, h1, l1;
                cvt_pair(x.x, x.y, h0, l0);
                cvt_pair(x.z, x.w, h1, l1);
                uint32_t sw = SWZ((uint32_t)(row * 128 + c4 * 8));
                *(uint2*)(smc + R_HI + sw) = make_uint2(h0, h1);
                *(uint2*)(smc + R_LO + sw) = make_uint2(l0, l1);
            }
        }
        // ---- convert V transposed: Vt[d][j] ----
        #pragma unroll
        for (int it = 0; it < 4; ++it) {
            int e = t + it * 256;
            int j = e >> 4, c4 = e & 15;
            float4 x = *(const float4*)(vb + (size_t)(j0 + j) * 64 + c4 * 4);
            float xs4[4] = {x.x, x.y, x.z, x.w};
            #pragma unroll
            for (int u = 0; u < 4; ++u) {
                int d = c4 * 4 + u;
                uint32_t sw = SWZ((uint32_t)(d * 128 + j * 2));
                __nv_bfloat16 vh = __float2bfloat16(xs4[u]);
                *(__nv_bfloat16*)(smc + VT_HI + sw) = vh;
                *(__nv_bfloat16*)(smc + VT_LO + sw) =
                    __float2bfloat16(xs4[u] - __bfloat162float(vh));
            }
        }
        __syncthreads();

        // ---- QK MMAs: zacc = Q K^T (3-split) ----
        float zacc[2][2][4];
        #pragma unroll
        for (int a = 0; a < 2; ++a)
            #pragma unroll
            for (int b = 0; b < 2; ++b)
                #pragma unroll
                for (int r = 0; r < 4; ++r) zacc[a][b][r] = 0.f;
        {
            const uint32_t APl[3] = {Q_HI, Q_HI, Q_LO};
            const uint32_t BPl[3] = {K_HI, K_LO, K_HI};
            #pragma unroll
            for (int p = 0; p < 3; ++p)
                #pragma unroll
                for (int kk = 0; kk < 4; ++kk) {
                    uint32_t A[2][4], B[2][2];
                    #pragma unroll
                    for (int mt = 0; mt < 2; ++mt)
                        ldmA(A[mt], sb + APl[p] +
                             (((uint32_t)((wi*32 + mt*16) << 7) + aoff + kk*32) ^ xl));
                    #pragma unroll
                    for (int nt = 0; nt < 2; ++nt)
                        ldmB(B[nt], sb + BPl[p] +
                             (((uint32_t)((wj*16 + nt*8) << 7) + boff + kk*32) ^ xl));
                    #pragma unroll
                    for (int mt = 0; mt < 2; ++mt)
                        #pragma unroll
                        for (int nt = 0; nt < 2; ++nt)
                            mma16816(zacc[mt][nt], A[mt], B[nt]);
                }
        }

        // ---- band halves: MMA into stage, then gather into zacc ----
        const uint32_t RPlA[3] = {Q_HI, Q_HI, Q_LO};
        const uint32_t RPlB[3] = {R_HI, R_LO, R_HI};
        #pragma unroll
        for (int half = 0; half < 2; ++half) {
            float bacc[2][2][4];
            #pragma unroll
            for (int a = 0; a < 2; ++a)
                #pragma unroll
                for (int b = 0; b < 2; ++b)
                    #pragma unroll
                    for (int r = 0; r < 4; ++r) bacc[a][b][r] = 0.f;
            #pragma unroll
            for (int p = 0; p < 3; ++p)
                #pragma unroll
                for (int kk = 0; kk < 4; ++kk) {
                    uint32_t A[2][4], B[2][2];
                    #pragma unroll
                    for (int mt = 0; mt < 2; ++mt)
                        ldmA(A[mt], sb + RPlA[p] +
                             (((uint32_t)((wi*32 + mt*16) << 7) + aoff + kk*32) ^ xl));
                    #pragma unroll
                    for (int nt = 0; nt < 2; ++nt)
                        ldmB(B[nt], sb + RPlB[p] + half * 8192 +
                             (((uint32_t)((wj*16 + nt*8) << 7) + boff + kk*32) ^ xl));
                    #pragma unroll
                    for (int mt = 0; mt < 2; ++mt)
                        #pragma unroll
                        for (int nt = 0; nt < 2; ++nt)
                            mma16816(bacc[mt][nt], A[mt], B[nt]);
                }
            // stage bacc (f32)
            #pragma unroll
            for (int mt = 0; mt < 2; ++mt)
                #pragma unroll
                for (int nt = 0; nt < 2; ++nt) {
                    int r0 = wi*32 + mt*16 + qr;
                    int m0 = wj*16 + nt*8 + qc;
                    *(float2*)&Pst[r0 * 64 + m0] =
                        make_float2(bacc[mt][nt][0], bacc[mt][nt][1]);
                    *(float2*)&Pst[(r0 + 8) * 64 + m0] =
                        make_float2(bacc[mt][nt][2], bacc[mt][nt][3]);
                }
            __syncthreads();
            // gather: half0 -> jj>=ii (m=ii-jj+63), half1 -> jj<ii (m2=ii-jj-1)
            #pragma unroll
            for (int mt = 0; mt < 2; ++mt)
                #pragma unroll
                for (int nt = 0; nt < 2; ++nt)
                    #pragma unroll
                    for (int r = 0; r < 4; ++r) {
                        int ii = wi*32 + mt*16 + qr + ((r >> 1) << 3);
                        int jj = wj*16 + nt*8 + qc + (r & 1);
                        if (half == 0) {
                            if (jj >= ii)
                                zacc[mt][nt][r] += Pst[ii * 64 + (ii - jj + 63)];
                        } else {
                            if (jj < ii)
                                zacc[mt][nt][r] += Pst[ii * 64 + (ii - jj - 1)];
                        }
                    }
            __syncthreads();   // stage reads done before reuse / S writes
        }

        // ---- s = 1 + z + 0.5 z^2 in-place; accumulate row sums ----
        #pragma unroll
        for (int mt = 0; mt < 2; ++mt)
            #pragma unroll
            for (int nt = 0; nt < 2; ++nt)
                #pragma unroll
                for (int r = 0; r < 4; ++r) {
                    float z = zacc[mt][nt][r];
                    float s = fmaf(z, fmaf(z, 0.5f, 1.f), 1.f);
                    zacc[mt][nt][r] = s;
                    dsum[mt * 2 + (r >> 1)] += s;
                }

        // ---- write S hi/lo (stage region now dead); row-based swizzle xs ----
        #pragma unroll
        for (int mt = 0; mt < 2; ++mt)
            #pragma unroll
            for (int nt = 0; nt < 2; ++nt) {
                int r0 = wi*32 + mt*16 + qr;
                int c0 = wj*16 + nt*8 + qc;
                uint32_t h0, l0, h1, l1;
                cvt_pair(zacc[mt][nt][0], zacc[mt][nt][1], h0, l0);
                cvt_pair(zacc[mt][nt][2], zacc[mt][nt][3], h1, l1);
                uint32_t off0 = ((uint32_t)(r0 * 128 + c0 * 2)) ^ xs;
                *(uint32_t*)(smc + S_HI + off0) = h0;
                *(uint32_t*)(smc + S_LO + off0) = l0;
                *(uint32_t*)(smc + S_HI + off0 + 1024) = h1;
                *(uint32_t*)(smc + S_LO + off0 + 1024) = l1;
            }
        __syncthreads();

        // ---- SV MMAs: O += S Vt^T (3-split), accum in regs ----
        {
            const uint32_t APl[3] = {S_HI, S_HI, S_LO};
            const uint32_t BPl[3] = {VT_HI, VT_LO, VT_HI};
            #pragma unroll
            for (int p = 0; p < 3; ++p)
                #pragma unroll
                for (int kk = 0; kk < 4; ++kk) {
                    uint32_t A[2][4], B[2][2];
                    #pragma unroll
                    for (int mt = 0; mt < 2; ++mt)
                        ldmA(A[mt], sb + APl[p] +
                             (((uint32_t)((wi*32 + mt*16) << 7) + aoff + kk*32) ^ xl));
                    #pragma unroll
                    for (int nt = 0; nt < 2; ++nt)
                        ldmB(B[nt], sb + BPl[p] +
                             (((uint32_t)((wj*16 + nt*8) << 7) + boff + kk*32) ^ xl));
                    #pragma unroll
                    for (int mt = 0; mt < 2; ++mt)
                        #pragma unroll
                        for (int nt = 0; nt < 2; ++nt)
                            mma16816(oacc[mt][nt], A[mt], B[nt]);
                }
        }
    }

    // ---- reduce denominators: over quad lanes, then across wj warps ----
    #pragma unroll
    for (int u = 0; u < 4; ++u) {
        float s = dsum[u];
        s += __shfl_xor_sync(0xffffffffu, s, 1);
        s += __shfl_xor_sync(0xffffffffu, s, 2);
        if ((lane & 3) == 0)
            atomicAdd(&Dsm[wi*32 + (u >> 1)*16 + qr + ((u & 1) << 3)], s);
    }
    __syncthreads();

    // ---- epilogue: divide and store ----
    #pragma unroll
    for (int mt = 0; mt < 2; ++mt)
        #pragma unroll
        for (int nt = 0; nt < 2; ++nt) {
            int ii = wi*32 + mt*16 + qr;
            int d0 = wj*16 + nt*8 + qc;
            float inv0 = 1.f / Dsm[ii];
            float inv1 = 1.f / Dsm[ii + 8];
            float* o0 = out + ((size_t)(bh * NSEQ + i0 + ii)) * 64 + d0;
            *(float2*)o0 = make_float2(oacc[mt][nt][0] * inv0, oacc[mt][nt][1] * inv0);
            *(float2*)(o0 + 8 * 64) =
                make_float2(oacc[mt][nt][2] * inv1, oacc[mt][nt][3] * inv1);
        }
}

extern "C" void kernel_launch(void* const* d_in, const int* in_sizes, int n_in,
                              void* d_out, int out_size)
{
    const float* q   = (const float*)d_in[0];
    const float* k   = (const float*)d_in[1];
    const float* v   = (const float*)d_in[2];
    // d_in[3] = drop_noise (unused)
    const float* rpe = (const float*)d_in[4];
    float* out = (float*)d_out;

    cudaFuncSetAttribute(fast_attn_hmma,
                         cudaFuncAttributeMaxDynamicSharedMemorySize, SMEM_BYTES);
    dim3 grid(NSEQ / BI, 16);   // 16 x 16 = 256 CTAs
    fast_attn_hmma<<<grid, 256, SMEM_BYTES>>>(q, k, v, rpe, out);
}

// round 6
// speedup vs baseline: 1.4225x; 1.2116x over previous
#include <cuda_runtime.h>
#include <cuda_bf16.h>
#include <cstdint>

// Degree-2 Taylor attention with RPE via warp-level mma.sync (bf16 x3-split).
// z_ij = q_i.k_j + q_i.rpe[i-j+1023]; s = 1+z+z^2/2; o = (S v)/rowsum(S).
// BI=BJ=64, grid 16 i-tiles x 16 bh, 256 threads (8 warps), 2 CTAs/SM.
// R6: Q_HI fragments cached in registers; V natural layout + ldmatrix.trans.

constexpr int NSEQ = 1024, BI = 64, BJ = 64, NT = NSEQ / BJ;

// smem byte offsets (tiles row-major bf16, 128B rows, XOR-16B swizzle)
constexpr int Q_HI = 0,      Q_LO = 8192;
constexpr int K_HI = 16384,  K_LO = 24576;
constexpr int R_HI = 32768,  R_LO = 49152;   // 128 rows x 128B each
constexpr int V_HI = 65536,  V_LO = 73728;   // V natural [j][d] 64x64
constexpr int S_HI = 81920,  S_LO = 90112;   // S 64x64 hi/lo
constexpr int STG  = 81920;                  // f32 band stage 64x64 (aliases S)
constexpr int DEN  = 98304;                  // 64 f32
constexpr int SMEM_BYTES = 98560;

#define SWZ(o) ((o) ^ ((((o) >> 7) & 7) << 4))

__device__ __forceinline__ uint32_t smem_u32(const void* p) {
    uint32_t a;
    asm("{ .reg .u64 t; cvta.to.shared.u64 t, %1; cvt.u32.u64 %0, t; }"
        : "=r"(a) : "l"(p));
    return a;
}
__device__ __forceinline__ void ldmA(uint32_t a[4], uint32_t addr) {
    asm volatile("ldmatrix.sync.aligned.m8n8.x4.shared.b16 {%0,%1,%2,%3}, [%4];"
                 : "=r"(a[0]), "=r"(a[1]), "=r"(a[2]), "=r"(a[3]) : "r"(addr));
}
__device__ __forceinline__ void ldmB(uint32_t b[2], uint32_t addr) {
    asm volatile("ldmatrix.sync.aligned.m8n8.x2.shared.b16 {%0,%1}, [%2];"
                 : "=r"(b[0]), "=r"(b[1]) : "r"(addr));
}
__device__ __forceinline__ void ldmBT(uint32_t b[2], uint32_t addr) {
    asm volatile("ldmatrix.sync.aligned.m8n8.x2.trans.shared.b16 {%0,%1}, [%2];"
                 : "=r"(b[0]), "=r"(b[1]) : "r"(addr));
}
__device__ __forceinline__ void mma16816(float d[4], const uint32_t a[4],
                                         const uint32_t b[2]) {
    asm volatile(
        "mma.sync.aligned.m16n8k16.row.col.f32.bf16.bf16.f32 "
        "{%0,%1,%2,%3}, {%4,%5,%6,%7}, {%8,%9}, {%0,%1,%2,%3};"
        : "+f"(d[0]), "+f"(d[1]), "+f"(d[2]), "+f"(d[3])
        : "r"(a[0]), "r"(a[1]), "r"(a[2]), "r"(a[3]), "r"(b[0]), "r"(b[1]));
}
__device__ __forceinline__ void cvt_pair(float a, float b, uint32_t& hi, uint32_t& lo) {
    __nv_bfloat162 h = __floats2bfloat162_rn(a, b);
    float2 hf = __bfloat1622float2(h);
    __nv_bfloat162 l = __floats2bfloat162_rn(a - hf.x, b - hf.y);
    hi = *(uint32_t*)&h;
    lo = *(uint32_t*)&l;
}

__global__ void __launch_bounds__(256, 2)
fast_attn_hmma(const float* __restrict__ q, const float* __restrict__ k,
               const float* __restrict__ v, const float* __restrict__ rpe,
               float* __restrict__ out)
{
    extern __shared__ __align__(1024) char smc[];
    const uint32_t sb = smem_u32(smc);
    float* Pst = (float*)(smc + STG);
    float* Dsm = (float*)(smc + DEN);

    const int bh = blockIdx.y;
    const int i0 = blockIdx.x * BI;
    const int t = threadIdx.x, lane = t & 31, w = t >> 5;
    const int wi = w >> 2, wj = w & 3;          // warp tile: rows wi*32, cols wj*16
    const int qr = lane >> 2, qc = (lane & 3) * 2;

    const uint32_t xl   = (uint32_t)(lane & 7) << 4;   // row-phase XOR (ldmatrix)
    const uint32_t xs   = (uint32_t)qr << 4;           // row-phase XOR (S stores)
    const uint32_t aoff = ((uint32_t)((lane & 7) + (lane & 8)) << 7) |
                          (((uint32_t)(lane >> 4) & 1) << 4);
    const uint32_t boff = ((uint32_t)(lane & 7) << 7) |
                          (((uint32_t)(lane >> 3) & 1) << 4);
    const uint32_t voff = (uint32_t)(lane & 15) << 7;  // trans-ldm row component

    const float* qb = q + (size_t)bh * NSEQ * 64;
    const float* kb = k + (size_t)bh * NSEQ * 64;
    const float* vb = v + (size_t)bh * NSEQ * 64;

    // ---- convert Q tile once (64x64 -> bf16 hi/lo) ----
    #pragma unroll
    for (int it = 0; it < 4; ++it) {
        int e = t + it * 256;
        int row = e >> 4, c4 = e & 15;
        float4 x = *(const float4*)(qb + (size_t)(i0 + row) * 64 + c4 * 4);
        uint32_t h0, l0, h1, l1;
        cvt_pair(x.x, x.y, h0, l0);
        cvt_pair(x.z, x.w, h1, l1);
        uint32_t sw = SWZ((uint32_t)(row * 128 + c4 * 8));
        *(uint2*)(smc + Q_HI + sw) = make_uint2(h0, h1);
        *(uint2*)(smc + Q_LO + sw) = make_uint2(l0, l1);
    }
    if (t < 64) Dsm[t] = 0.f;
    __syncthreads();

    // ---- preload Q_HI A-fragments (tile-invariant) ----
    uint32_t qA[2][4][4];
    #pragma unroll
    for (int mt = 0; mt < 2; ++mt)
        #pragma unroll
        for (int kk = 0; kk < 4; ++kk)
            ldmA(qA[mt][kk], sb + Q_HI +
                 ((((uint32_t)(wi*32 + mt*16) << 7) + aoff + kk*32) ^ xl));

    float oacc[2][2][4];
    float dsum[4];
    #pragma unroll
    for (int a = 0; a < 2; ++a)
        #pragma unroll
        for (int b = 0; b < 2; ++b)
            #pragma unroll
            for (int r = 0; r < 4; ++r) oacc[a][b][r] = 0.f;
    #pragma unroll
    for (int u = 0; u < 4; ++u) dsum[u] = 0.f;

    for (int tile = 0; tile < NT; ++tile) {
        const int j0 = tile * BJ;
        __syncthreads();   // prev SV reads of S/V done; smem reuse safe

        // ---- convert K tile ----
        #pragma unroll
        for (int it = 0; it < 4; ++it) {
            int e = t + it * 256;
            int row = e >> 4, c4 = e & 15;
            float4 x = *(const float4*)(kb + (size_t)(j0 + row) * 64 + c4 * 4);
            uint32_t h0, l0, h1, l1;
            cvt_pair(x.x, x.y, h0, l0);
            cvt_pair(x.z, x.w, h1, l1);
            uint32_t sw = SWZ((uint32_t)(row * 128 + c4 * 8));
            *(uint2*)(smc + K_HI + sw) = make_uint2(h0, h1);
            *(uint2*)(smc + K_LO + sw) = make_uint2(l0, l1);
        }
        // ---- convert rpe window rows r0..r0+127 ----
        {
            const int r0 = i0 - j0 + 960;
            #pragma unroll
            for (int it = 0; it < 8; ++it) {
                int e = t + it * 256;
                int row = e >> 4, c4 = e & 15;
                int gr = r0 + row; if (gr > 2046) gr = 2046;  // row 127 never gathered
                float4 x = *(const float4*)(rpe + (size_t)gr * 64 + c4 * 4);
                uint32_t h0, l0, h1, l1;
                cvt_pair(x.x, x.y, h0, l0);
                cvt_pair(x.z, x.w, h1, l1);
                uint32_t sw = SWZ((uint32_t)(row * 128 + c4 * 8));
                *(uint2*)(smc + R_HI + sw) = make_uint2(h0, h1);
                *(uint2*)(smc + R_LO + sw) = make_uint2(l0, l1);
            }
        }
        // ---- convert V tile (natural [j][d] layout, hi/lo) ----
        #pragma unroll
        for (int it = 0; it < 4; ++it) {
            int e = t + it * 256;
            int row = e >> 4, c4 = e & 15;
            float4 x = *(const float4*)(vb + (size_t)(j0 + row) * 64 + c4 * 4);
            uint32_t h0, l0, h1, l1;
            cvt_pair(x.x, x.y, h0, l0);
            cvt_pair(x.z, x.w, h1, l1);
            uint32_t sw = SWZ((uint32_t)(row * 128 + c4 * 8));
            *(uint2*)(smc + V_HI + sw) = make_uint2(h0, h1);
            *(uint2*)(smc + V_LO + sw) = make_uint2(l0, l1);
        }
        __syncthreads();

        // ---- QK MMAs: zacc = Q K^T (3-split; p0/p1 use reg Q_HI) ----
        float zacc[2][2][4];
        #pragma unroll
        for (int a = 0; a < 2; ++a)
            #pragma unroll
            for (int b = 0; b < 2; ++b)
                #pragma unroll
                for (int r = 0; r < 4; ++r) zacc[a][b][r] = 0.f;
        #pragma unroll
        for (int p = 0; p < 2; ++p) {
            uint32_t Bb = (p == 0) ? K_HI : K_LO;
            #pragma unroll
            for (int kk = 0; kk < 4; ++kk) {
                uint32_t B[2][2];
                #pragma unroll
                for (int nt = 0; nt < 2; ++nt)
                    ldmB(B[nt], sb + Bb +
                         ((((uint32_t)(wj*16 + nt*8) << 7) + boff + kk*32) ^ xl));
                #pragma unroll
                for (int mt = 0; mt < 2; ++mt)
                    #pragma unroll
                    for (int nt = 0; nt < 2; ++nt)
                        mma16816(zacc[mt][nt], qA[mt][kk], B[nt]);
            }
        }
        #pragma unroll
        for (int kk = 0; kk < 4; ++kk) {   // p2: Q_LO x K_HI
            uint32_t A[2][4], B[2][2];
            #pragma unroll
            for (int mt = 0; mt < 2; ++mt)
                ldmA(A[mt], sb + Q_LO +
                     ((((uint32_t)(wi*32 + mt*16) << 7) + aoff + kk*32) ^ xl));
            #pragma unroll
            for (int nt = 0; nt < 2; ++nt)
                ldmB(B[nt], sb + K_HI +
                     ((((uint32_t)(wj*16 + nt*8) << 7) + boff + kk*32) ^ xl));
            #pragma unroll
            for (int mt = 0; mt < 2; ++mt)
                #pragma unroll
                for (int nt = 0; nt < 2; ++nt)
                    mma16816(zacc[mt][nt], A[mt], B[nt]);
        }

        // ---- band halves: MMA into stage, then gather into zacc ----
        #pragma unroll
        for (int half = 0; half < 2; ++half) {
            float bacc[2][2][4];
            #pragma unroll
            for (int a = 0; a < 2; ++a)
                #pragma unroll
                for (int b = 0; b < 2; ++b)
                    #pragma unroll
                    for (int r = 0; r < 4; ++r) bacc[a][b][r] = 0.f;
            #pragma unroll
            for (int p = 0; p < 2; ++p) {     // p0: Qhi·Rhi, p1: Qhi·Rlo
                uint32_t Bb = ((p == 0) ? R_HI : R_LO) + half * 8192;
                #pragma unroll
                for (int kk = 0; kk < 4; ++kk) {
                    uint32_t B[2][2];
                    #pragma unroll
                    for (int nt = 0; nt < 2; ++nt)
                        ldmB(B[nt], sb + Bb +
                             ((((uint32_t)(wj*16 + nt*8) << 7) + boff + kk*32) ^ xl));
                    #pragma unroll
                    for (int mt = 0; mt < 2; ++mt)
                        #pragma unroll
                        for (int nt = 0; nt < 2; ++nt)
                            mma16816(bacc[mt][nt], qA[mt][kk], B[nt]);
                }
            }
            #pragma unroll
            for (int kk = 0; kk < 4; ++kk) {  // p2: Q_LO x R_HI
                uint32_t A[2][4], B[2][2];
                #pragma unroll
                for (int mt = 0; mt < 2; ++mt)
                    ldmA(A[mt], sb + Q_LO +
                         ((((uint32_t)(wi*32 + mt*16) << 7) + aoff + kk*32) ^ xl));
                #pragma unroll
                for (int nt = 0; nt < 2; ++nt)
                    ldmB(B[nt], sb + R_HI + half * 8192 +
                         ((((uint32_t)(wj*16 + nt*8) << 7) + boff + kk*32) ^ xl));
                #pragma unroll
                for (int mt = 0; mt < 2; ++mt)
                    #pragma unroll
                    for (int nt = 0; nt < 2; ++nt)
                        mma16816(bacc[mt][nt], A[mt], B[nt]);
            }
            // stage bacc (f32)
            #pragma unroll
            for (int mt = 0; mt < 2; ++mt)
                #pragma unroll
                for (int nt = 0; nt < 2; ++nt) {
                    int r0 = wi*32 + mt*16 + qr;
                    int m0 = wj*16 + nt*8 + qc;
                    *(float2*)&Pst[r0 * 64 + m0] =
                        make_float2(bacc[mt][nt][0], bacc[mt][nt][1]);
                    *(float2*)&Pst[(r0 + 8) * 64 + m0] =
                        make_float2(bacc[mt][nt][2], bacc[mt][nt][3]);
                }
            __syncthreads();
            // gather: half0 -> jj>=ii (m=ii-jj+63), half1 -> jj<ii (m=ii-jj-1)
            #pragma unroll
            for (int mt = 0; mt < 2; ++mt)
                #pragma unroll
                for (int nt = 0; nt < 2; ++nt)
                    #pragma unroll
                    for (int r = 0; r < 4; ++r) {
                        int ii = wi*32 + mt*16 + qr + ((r >> 1) << 3);
                        int jj = wj*16 + nt*8 + qc + (r & 1);
                        if (half == 0) {
                            if (jj >= ii)
                                zacc[mt][nt][r] += Pst[ii * 64 + (ii - jj + 63)];
                        } else {
                            if (jj < ii)
                                zacc[mt][nt][r] += Pst[ii * 64 + (ii - jj - 1)];
                        }
                    }
            __syncthreads();   // stage reads done before reuse / S writes
        }

        // ---- s = 1 + z + 0.5 z^2 in-place; accumulate row sums ----
        #pragma unroll
        for (int mt = 0; mt < 2; ++mt)
            #pragma unroll
            for (int nt = 0; nt < 2; ++nt)
                #pragma unroll
                for (int r = 0; r < 4; ++r) {
                    float z = zacc[mt][nt][r];
                    float s = fmaf(z, fmaf(z, 0.5f, 1.f), 1.f);
                    zacc[mt][nt][r] = s;
                    dsum[mt * 2 + (r >> 1)] += s;
                }

        // ---- write S hi/lo (stage region now dead); row-based swizzle xs ----
        #pragma unroll
        for (int mt = 0; mt < 2; ++mt)
            #pragma unroll
            for (int nt = 0; nt < 2; ++nt) {
                int r0 = wi*32 + mt*16 + qr;
                int c0 = wj*16 + nt*8 + qc;
                uint32_t h0, l0, h1, l1;
                cvt_pair(zacc[mt][nt][0], zacc[mt][nt][1], h0, l0);
                cvt_pair(zacc[mt][nt][2], zacc[mt][nt][3], h1, l1);
                uint32_t off0 = ((uint32_t)(r0 * 128 + c0 * 2)) ^ xs;
                *(uint32_t*)(smc + S_HI + off0) = h0;
                *(uint32_t*)(smc + S_LO + off0) = l0;
                *(uint32_t*)(smc + S_HI + off0 + 1024) = h1;
                *(uint32_t*)(smc + S_LO + off0 + 1024) = l1;
            }
        __syncthreads();

        // ---- SV MMAs: O += S V (3-split), B via ldmatrix.trans on natural V ----
        {
            const uint32_t APl[3] = {S_HI, S_HI, S_LO};
            const uint32_t BPl[3] = {V_HI, V_LO, V_HI};
            #pragma unroll
            for (int p = 0; p < 3; ++p)
                #pragma unroll
                for (int kk = 0; kk < 4; ++kk) {
                    uint32_t A[2][4], B[2][2];
                    #pragma unroll
                    for (int mt = 0; mt < 2; ++mt)
                        ldmA(A[mt], sb + APl[p] +
                             (((uint32_t)((wi*32 + mt*16) << 7) + aoff + kk*32) ^ xl));
                    #pragma unroll
                    for (int nt = 0; nt < 2; ++nt)
                        ldmBT(B[nt], sb + BPl[p] +
                              ((((uint32_t)(kk*16) << 7) + voff +
                                (uint32_t)(wj*32 + nt*16)) ^ xl));
                    #pragma unroll
                    for (int mt = 0; mt < 2; ++mt)
                        #pragma unroll
                        for (int nt = 0; nt < 2; ++nt)
                            mma16816(oacc[mt][nt], A[mt], B[nt]);
                }
        }
    }

    // ---- reduce denominators: over quad lanes, then across wj warps ----
    #pragma unroll
    for (int u = 0; u < 4; ++u) {
        float s = dsum[u];
        s += __shfl_xor_sync(0xffffffffu, s, 1);
        s += __shfl_xor_sync(0xffffffffu, s, 2);
        if ((lane & 3) == 0)
            atomicAdd(&Dsm[wi*32 + (u >> 1)*16 + qr + ((u & 1) << 3)], s);
    }
    __syncthreads();

    // ---- epilogue: divide and store ----
    #pragma unroll
    for (int mt = 0; mt < 2; ++mt)
        #pragma unroll
        for (int nt = 0; nt < 2; ++nt) {
            int ii = wi*32 + mt*16 + qr;
            int d0 = wj*16 + nt*8 + qc;
            float inv0 = 1.f / Dsm[ii];
            float inv1 = 1.f / Dsm[ii + 8];
            float* o0 = out + ((size_t)(bh * NSEQ + i0 + ii)) * 64 + d0;
            *(float2*)o0 = make_float2(oacc[mt][nt][0] * inv0, oacc[mt][nt][1] * inv0);
            *(float2*)(o0 + 8 * 64) =
                make_float2(oacc[mt][nt][2] * inv1, oacc[mt][nt][3] * inv1);
        }
}

extern "C" void kernel_launch(void* const* d_in, const int* in_sizes, int n_in,
                              void* d_out, int out_size)
{
    const float* q   = (const float*)d_in[0];
    const float* k   = (const float*)d_in[1];
    const float* v   = (const float*)d_in[2];
    // d_in[3] = drop_noise (unused)
    const float* rpe = (const float*)d_in[4];
    float* out = (float*)d_out;

    cudaFuncSetAttribute(fast_attn_hmma,
                         cudaFuncAttributeMaxDynamicSharedMemorySize, SMEM_BYTES);
    dim3 grid(NSEQ / BI, 16);   // 16 x 16 = 256 CTAs
    fast_attn_hmma<<<grid, 256, SMEM_BYTES>>>(q, k, v, rpe, out);
}

// round 7
// speedup vs baseline: 2.3617x; 1.6602x over previous
#include <cuda_runtime.h>
#include <cuda_bf16.h>
#include <cstdint>

// Degree-2 Taylor attention with RPE via warp-level mma.sync (bf16 x3-split)
// + rolling band ring: band[i][u]=q_i.rpe[u] computed once per u-column.
// BI=128, BJ=64, 512 threads (16 warps), grid 8 x 16 = 128 CTAs, 1 CTA/SM.

constexpr int NSEQ = 1024, BI = 128, BJ = 64, NT = NSEQ / BJ;
constexpr int RSTR = 200;   // ring stride in floats

// smem byte offsets
constexpr int Q_HI = 0,      Q_LO = 16384;   // 128x64 bf16
constexpr int K_HI = 32768,  K_LO = 40960;   // 64x64
constexpr int R_HI = 49152,  R_LO = 57344;   // 64 rpe rows
constexpr int V_HI = 65536,  V_LO = 73728;   // 64x64 natural
constexpr int S_HI = 81920,  S_LO = 98304;   // 128x64
constexpr int RING = 114688;                 // 128 x 200 f32 ring
constexpr int DEN  = RING + 128 * RSTR * 4;  // 217088
constexpr int SMEM_BYTES = DEN + 512;        // 217600

#define SWZ(o) ((o) ^ ((((o) >> 7) & 7) << 4))

__device__ __forceinline__ uint32_t smem_u32(const void* p) {
    uint32_t a;
    asm("{ .reg .u64 t; cvta.to.shared.u64 t, %1; cvt.u32.u64 %0, t; }"
        : "=r"(a) : "l"(p));
    return a;
}
__device__ __forceinline__ void ldmA(uint32_t a[4], uint32_t addr) {
    asm volatile("ldmatrix.sync.aligned.m8n8.x4.shared.b16 {%0,%1,%2,%3}, [%4];"
                 : "=r"(a[0]), "=r"(a[1]), "=r"(a[2]), "=r"(a[3]) : "r"(addr));
}
__device__ __forceinline__ void ldmB(uint32_t b[2], uint32_t addr) {
    asm volatile("ldmatrix.sync.aligned.m8n8.x2.shared.b16 {%0,%1}, [%2];"
                 : "=r"(b[0]), "=r"(b[1]) : "r"(addr));
}
__device__ __forceinline__ void ldmBT(uint32_t b[2], uint32_t addr) {
    asm volatile("ldmatrix.sync.aligned.m8n8.x2.trans.shared.b16 {%0,%1}, [%2];"
                 : "=r"(b[0]), "=r"(b[1]) : "r"(addr));
}
__device__ __forceinline__ void mma16816(float d[4], const uint32_t a[4],
                                         const uint32_t b[2]) {
    asm volatile(
        "mma.sync.aligned.m16n8k16.row.col.f32.bf16.bf16.f32 "
        "{%0,%1,%2,%3}, {%4,%5,%6,%7}, {%8,%9}, {%0,%1,%2,%3};"
        : "+f"(d[0]), "+f"(d[1]), "+f"(d[2]), "+f"(d[3])
        : "r"(a[0]), "r"(a[1]), "r"(a[2]), "r"(a[3]), "r"(b[0]), "r"(b[1]));
}
__device__ __forceinline__ void cvt_pair(float a, float b, uint32_t& hi, uint32_t& lo) {
    __nv_bfloat162 h = __floats2bfloat162_rn(a, b);
    float2 hf = __bfloat1622float2(h);
    __nv_bfloat162 l = __floats2bfloat162_rn(a - hf.x, b - hf.y);
    hi = *(uint32_t*)&h;
    lo = *(uint32_t*)&l;
}

__global__ void __launch_bounds__(512, 1)
fast_attn_hmma(const float* __restrict__ q, const float* __restrict__ k,
               const float* __restrict__ v, const float* __restrict__ rpe,
               float* __restrict__ out)
{
    extern __shared__ __align__(1024) char smc[];
    const uint32_t sb = smem_u32(smc);
    float* Pring = (float*)(smc + RING);
    float* Dsm = (float*)(smc + DEN);

    const int bh = blockIdx.y;
    const int i0 = blockIdx.x * BI;
    const int t = threadIdx.x, lane = t & 31, w = t >> 5;
    const int wi = w >> 2, wj = w & 3;   // warp rows wi*32..+31, cols wj*16..+15
    const int qr = lane >> 2, qc = (lane & 3) * 2;

    const uint32_t xl   = (uint32_t)(lane & 7) << 4;
    const uint32_t xs   = (uint32_t)qr << 4;
    const uint32_t aoff = ((uint32_t)((lane & 7) + (lane & 8)) << 7) |
                          (((uint32_t)(lane >> 4) & 1) << 4);
    const uint32_t boff = ((uint32_t)(lane & 7) << 7) |
                          (((uint32_t)(lane >> 3) & 1) << 4);
    const uint32_t voff = (uint32_t)(lane & 15) << 7;

    const float* qb = q + (size_t)bh * NSEQ * 64;
    const float* kb = k + (size_t)bh * NSEQ * 64;
    const float* vb = v + (size_t)bh * NSEQ * 64;

    // ---- convert Q tile once (128x64 -> bf16 hi/lo) ----
    #pragma unroll
    for (int it = 0; it < 4; ++it) {
        int e = t + it * 512;
        int row = e >> 4, c4 = e & 15;
        float4 x = *(const float4*)(qb + (size_t)(i0 + row) * 64 + c4 * 4);
        uint32_t h0, l0, h1, l1;
        cvt_pair(x.x, x.y, h0, l0);
        cvt_pair(x.z, x.w, h1, l1);
        uint32_t sw = SWZ((uint32_t)(row * 128 + c4 * 8));
        *(uint2*)(smc + Q_HI + sw) = make_uint2(h0, h1);
        *(uint2*)(smc + Q_LO + sw) = make_uint2(l0, l1);
    }
    if (t < 128) Dsm[t] = 0.f;
    __syncthreads();

    // ---- preload Q_HI A-fragments (tile-invariant) ----
    uint32_t qA[2][4][4];
    #pragma unroll
    for (int mt = 0; mt < 2; ++mt)
        #pragma unroll
        for (int kk = 0; kk < 4; ++kk)
            ldmA(qA[mt][kk], sb + Q_HI +
                 ((((uint32_t)(wi*32 + mt*16) << 7) + aoff + kk*32) ^ xl));

    float oacc[2][2][4];
    float dsum[4];
    #pragma unroll
    for (int a = 0; a < 2; ++a)
        #pragma unroll
        for (int b = 0; b < 2; ++b)
            #pragma unroll
            for (int r = 0; r < 4; ++r) oacc[a][b][r] = 0.f;
    #pragma unroll
    for (int u = 0; u < 4; ++u) dsum[u] = 0.f;

    for (int tile = 0; tile < NT; ++tile) {
        const int j0 = tile * BJ;
        __syncthreads();   // prev SV done with S/V; K/V/R reuse safe

        // ---- convert K tile ----
        #pragma unroll
        for (int it = 0; it < 2; ++it) {
            int e = t + it * 512;
            int row = e >> 4, c4 = e & 15;
            float4 x = *(const float4*)(kb + (size_t)(j0 + row) * 64 + c4 * 4);
            uint32_t h0, l0, h1, l1;
            cvt_pair(x.x, x.y, h0, l0);
            cvt_pair(x.z, x.w, h1, l1);
            uint32_t sw = SWZ((uint32_t)(row * 128 + c4 * 8));
            *(uint2*)(smc + K_HI + sw) = make_uint2(h0, h1);
            *(uint2*)(smc + K_LO + sw) = make_uint2(l0, l1);
        }
        // ---- convert V tile (natural [j][d]) ----
        #pragma unroll
        for (int it = 0; it < 2; ++it) {
            int e = t + it * 512;
            int row = e >> 4, c4 = e & 15;
            float4 x = *(const float4*)(vb + (size_t)(j0 + row) * 64 + c4 * 4);
            uint32_t h0, l0, h1, l1;
            cvt_pair(x.x, x.y, h0, l0);
            cvt_pair(x.z, x.w, h1, l1);
            uint32_t sw = SWZ((uint32_t)(row * 128 + c4 * 8));
            *(uint2*)(smc + V_HI + sw) = make_uint2(h0, h1);
            *(uint2*)(smc + V_LO + sw) = make_uint2(l0, l1);
        }

        // ---- band ring: compute new u-columns (3 groups at tile 0, else 1) ----
        const int ngroups = (tile == 0) ? 3 : 1;
        for (int g = 0; g < ngroups; ++g) {
            const int ustart = i0 + 960 - 64 * tile + 64 * g;
            // convert rpe rows ustart..ustart+63
            #pragma unroll
            for (int it = 0; it < 2; ++it) {
                int e = t + it * 512;
                int row = e >> 4, c4 = e & 15;
                int gr = ustart + row; if (gr > 2046) gr = 2046;  // top col unused
                float4 x = *(const float4*)(rpe + (size_t)gr * 64 + c4 * 4);
                uint32_t h0, l0, h1, l1;
                cvt_pair(x.x, x.y, h0, l0);
                cvt_pair(x.z, x.w, h1, l1);
                uint32_t sw = SWZ((uint32_t)(row * 128 + c4 * 8));
                *(uint2*)(smc + R_HI + sw) = make_uint2(h0, h1);
                *(uint2*)(smc + R_LO + sw) = make_uint2(l0, l1);
            }
            __syncthreads();   // R (and on g=0: K/V) visible

            // band MMA: bacc = Q x Rg^T (3-split)
            float bacc[2][2][4];
            #pragma unroll
            for (int a = 0; a < 2; ++a)
                #pragma unroll
                for (int b = 0; b < 2; ++b)
                    #pragma unroll
                    for (int r = 0; r < 4; ++r) bacc[a][b][r] = 0.f;
            #pragma unroll
            for (int p = 0; p < 2; ++p) {      // qA x R_HI, qA x R_LO
                uint32_t Bb = (p == 0) ? R_HI : R_LO;
                #pragma unroll
                for (int kk = 0; kk < 4; ++kk) {
                    uint32_t B[2][2];
                    #pragma unroll
                    for (int nt = 0; nt < 2; ++nt)
                        ldmB(B[nt], sb + Bb +
                             ((((uint32_t)(wj*16 + nt*8) << 7) + boff + kk*32) ^ xl));
                    #pragma unroll
                    for (int mt = 0; mt < 2; ++mt)
                        #pragma unroll
                        for (int nt = 0; nt < 2; ++nt)
                            mma16816(bacc[mt][nt], qA[mt][kk], B[nt]);
                }
            }
            #pragma unroll
            for (int kk = 0; kk < 4; ++kk) {   // Q_LO x R_HI
                uint32_t A[2][4], B[2][2];
                #pragma unroll
                for (int mt = 0; mt < 2; ++mt)
                    ldmA(A[mt], sb + Q_LO +
                         ((((uint32_t)(wi*32 + mt*16) << 7) + aoff + kk*32) ^ xl));
                #pragma unroll
                for (int nt = 0; nt < 2; ++nt)
                    ldmB(B[nt], sb + R_HI +
                         ((((uint32_t)(wj*16 + nt*8) << 7) + boff + kk*32) ^ xl));
                #pragma unroll
                for (int mt = 0; mt < 2; ++mt)
                    #pragma unroll
                    for (int nt = 0; nt < 2; ++nt)
                        mma16816(bacc[mt][nt], A[mt], B[nt]);
            }
            // stage into ring (base multiple of 64 -> no wrap)
            {
                const int base_s = ustart % 192;
                #pragma unroll
                for (int mt = 0; mt < 2; ++mt)
                    #pragma unroll
                    for (int nt = 0; nt < 2; ++nt) {
                        int row = wi*32 + mt*16 + qr;
                        int slot = base_s + wj*16 + nt*8 + qc;
                        *(float2*)&Pring[row * RSTR + slot] =
                            make_float2(bacc[mt][nt][0], bacc[mt][nt][1]);
                        *(float2*)&Pring[(row + 8) * RSTR + slot] =
                            make_float2(bacc[mt][nt][2], bacc[mt][nt][3]);
                    }
            }
            __syncthreads();   // ring staged (and R free for next group)
        }

        // ---- QK MMAs: zacc = Q K^T (3-split) ----
        float zacc[2][2][4];
        #pragma unroll
        for (int a = 0; a < 2; ++a)
            #pragma unroll
            for (int b = 0; b < 2; ++b)
                #pragma unroll
                for (int r = 0; r < 4; ++r) zacc[a][b][r] = 0.f;
        #pragma unroll
        for (int p = 0; p < 2; ++p) {
            uint32_t Bb = (p == 0) ? K_HI : K_LO;
            #pragma unroll
            for (int kk = 0; kk < 4; ++kk) {
                uint32_t B[2][2];
                #pragma unroll
                for (int nt = 0; nt < 2; ++nt)
                    ldmB(B[nt], sb + Bb +
                         ((((uint32_t)(wj*16 + nt*8) << 7) + boff + kk*32) ^ xl));
                #pragma unroll
                for (int mt = 0; mt < 2; ++mt)
                    #pragma unroll
                    for (int nt = 0; nt < 2; ++nt)
                        mma16816(zacc[mt][nt], qA[mt][kk], B[nt]);
            }
        }
        #pragma unroll
        for (int kk = 0; kk < 4; ++kk) {       // Q_LO x K_HI
            uint32_t A[2][4], B[2][2];
            #pragma unroll
            for (int mt = 0; mt < 2; ++mt)
                ldmA(A[mt], sb + Q_LO +
                     ((((uint32_t)(wi*32 + mt*16) << 7) + aoff + kk*32) ^ xl));
            #pragma unroll
            for (int nt = 0; nt < 2; ++nt)
                ldmB(B[nt], sb + K_HI +
                     ((((uint32_t)(wj*16 + nt*8) << 7) + boff + kk*32) ^ xl));
            #pragma unroll
            for (int mt = 0; mt < 2; ++mt)
                #pragma unroll
                for (int nt = 0; nt < 2; ++nt)
                    mma16816(zacc[mt][nt], A[mt], B[nt]);
        }

        // ---- gather band from ring; s-transform; S store ----
        {
            int gb = (i0 - 64 * tile + 1023) % 192;   // in {63,127,191}
            #pragma unroll
            for (int mt = 0; mt < 2; ++mt)
                #pragma unroll
                for (int nt = 0; nt < 2; ++nt)
                    #pragma unroll
                    for (int r = 0; r < 4; ++r) {
                        int ii = wi*32 + mt*16 + qr + ((r >> 1) << 3);
                        int jj = wj*16 + nt*8 + qc + (r & 1);
                        int slot = gb + ii - jj;
                        if (slot >= 192) slot -= 192;
                        zacc[mt][nt][r] += Pring[ii * RSTR + slot];
                    }
        }
        #pragma unroll
        for (int mt = 0; mt < 2; ++mt)
            #pragma unroll
            for (int nt = 0; nt < 2; ++nt)
                #pragma unroll
                for (int r = 0; r < 4; ++r) {
                    float z = zacc[mt][nt][r];
                    float s = fmaf(z, fmaf(z, 0.5f, 1.f), 1.f);
                    zacc[mt][nt][r] = s;
                    dsum[mt * 2 + (r >> 1)] += s;
                }
        #pragma unroll
        for (int mt = 0; mt < 2; ++mt)
            #pragma unroll
            for (int nt = 0; nt < 2; ++nt) {
                int r0 = wi*32 + mt*16 + qr;
                int c0 = wj*16 + nt*8 + qc;
                uint32_t h0, l0, h1, l1;
                cvt_pair(zacc[mt][nt][0], zacc[mt][nt][1], h0, l0);
                cvt_pair(zacc[mt][nt][2], zacc[mt][nt][3], h1, l1);
                uint32_t off0 = ((uint32_t)(r0 * 128 + c0 * 2)) ^ xs;
                *(uint32_t*)(smc + S_HI + off0) = h0;
                *(uint32_t*)(smc + S_LO + off0) = l0;
                *(uint32_t*)(smc + S_HI + off0 + 1024) = h1;
                *(uint32_t*)(smc + S_LO + off0 + 1024) = l1;
            }
        __syncthreads();

        // ---- SV MMAs: O += S V (3-split, S_HI/V_HI frags cached) ----
        {
            uint32_t sA[2][4][4];
            #pragma unroll
            for (int mt = 0; mt < 2; ++mt)
                #pragma unroll
                for (int kk = 0; kk < 4; ++kk)
                    ldmA(sA[mt][kk], sb + S_HI +
                         ((((uint32_t)(wi*32 + mt*16) << 7) + aoff + kk*32) ^ xl));
            uint32_t vB[4][2][2];
            #pragma unroll
            for (int kk = 0; kk < 4; ++kk)
                #pragma unroll
                for (int nt = 0; nt < 2; ++nt)
                    ldmBT(vB[kk][nt], sb + V_HI +
                          ((((uint32_t)(kk*16) << 7) + voff +
                            (uint32_t)(wj*32 + nt*16)) ^ xl));
            // pass0: S_HI x V_HI
            #pragma unroll
            for (int kk = 0; kk < 4; ++kk)
                #pragma unroll
                for (int mt = 0; mt < 2; ++mt)
                    #pragma unroll
                    for (int nt = 0; nt < 2; ++nt)
                        mma16816(oacc[mt][nt], sA[mt][kk], vB[kk][nt]);
            // pass1: S_HI x V_LO
            #pragma unroll
            for (int kk = 0; kk < 4; ++kk) {
                uint32_t B[2][2];
                #pragma unroll
                for (int nt = 0; nt < 2; ++nt)
                    ldmBT(B[nt], sb + V_LO +
                          ((((uint32_t)(kk*16) << 7) + voff +
                            (uint32_t)(wj*32 + nt*16)) ^ xl));
                #pragma unroll
                for (int mt = 0; mt < 2; ++mt)
                    #pragma unroll
                    for (int nt = 0; nt < 2; ++nt)
                        mma16816(oacc[mt][nt], sA[mt][kk], B[nt]);
            }
            // pass2: S_LO x V_HI
            #pragma unroll
            for (int kk = 0; kk < 4; ++kk) {
                uint32_t A[2][4];
                #pragma unroll
                for (int mt = 0; mt < 2; ++mt)
                    ldmA(A[mt], sb + S_LO +
                         ((((uint32_t)(wi*32 + mt*16) << 7) + aoff + kk*32) ^ xl));
                #pragma unroll
                for (int mt = 0; mt < 2; ++mt)
                    #pragma unroll
                    for (int nt = 0; nt < 2; ++nt)
                        mma16816(oacc[mt][nt], A[mt], vB[kk][nt]);
            }
        }
    }

    // ---- reduce denominators ----
    #pragma unroll
    for (int u = 0; u < 4; ++u) {
        float s = dsum[u];
        s += __shfl_xor_sync(0xffffffffu, s, 1);
        s += __shfl_xor_sync(0xffffffffu, s, 2);
        if ((lane & 3) == 0)
            atomicAdd(&Dsm[wi*32 + (u >> 1)*16 + qr + ((u & 1) << 3)], s);
    }
    __syncthreads();

    // ---- epilogue ----
    #pragma unroll
    for (int mt = 0; mt < 2; ++mt)
        #pragma unroll
        for (int nt = 0; nt < 2; ++nt) {
            int ii = wi*32 + mt*16 + qr;
            int d0 = wj*16 + nt*8 + qc;
            float inv0 = 1.f / Dsm[ii];
            float inv1 = 1.f / Dsm[ii + 8];
            float* o0 = out + ((size_t)(bh * NSEQ + i0 + ii)) * 64 + d0;
            *(float2*)o0 = make_float2(oacc[mt][nt][0] * inv0, oacc[mt][nt][1] * inv0);
            *(float2*)(o0 + 8 * 64) =
                make_float2(oacc[mt][nt][2] * inv1, oacc[mt][nt][3] * inv1);
        }
}

extern "C" void kernel_launch(void* const* d_in, const int* in_sizes, int n_in,
                              void* d_out, int out_size)
{
    const float* q   = (const float*)d_in[0];
    const float* k   = (const float*)d_in[1];
    const float* v   = (const float*)d_in[2];
    // d_in[3] = drop_noise (unused)
    const float* rpe = (const float*)d_in[4];
    float* out = (float*)d_out;

    cudaFuncSetAttribute(fast_attn_hmma,
                         cudaFuncAttributeMaxDynamicSharedMemorySize, SMEM_BYTES);
    dim3 grid(NSEQ / BI, 16);   // 8 x 16 = 128 CTAs, one wave
    fast_attn_hmma<<<grid, 512, SMEM_BYTES>>>(q, k, v, rpe, out);
}